// round 5
// baseline (speedup 1.0000x reference)
#include <cuda_runtime.h>
#include <cuda_bf16.h>
#include <cstdint>

#define SEQ 2048
#define NB  32
#define DIM 128
#define NTOK (NB*SEQ)
#define TOK 64          // tokens per CTA

// row stride for smem tiles: 136 bf16 = 272 bytes (16B aligned rows, conflict-free)
#define RS 136
#define RSB (RS*2)

// ---------------- scratch (no allocations allowed) ----------------
__device__ float g_h0[NTOK*DIM];
__device__ float g_h1[NTOK*DIM];
__device__ float g_part[NB*8*DIM];
// prepared weight images: bf16 hi/lo, [n][k] row-major, unpadded
__device__ __align__(16) __nv_bfloat16 g_Bhi[4][DIM*DIM];
__device__ __align__(16) __nv_bfloat16 g_Blo[4][DIM*DIM];

// ---------------- helpers ----------------
__device__ __forceinline__ uint32_t smem_u32(const void* p) {
    uint32_t a;
    asm("{ .reg .u64 t; cvta.to.shared.u64 t, %1; cvt.u32.u64 %0, t; }" : "=r"(a) : "l"(p));
    return a;
}
__device__ __forceinline__ void sts128(uint32_t addr, uint4 v) {
    asm volatile("st.shared.v4.b32 [%0], {%1,%2,%3,%4};" :: "r"(addr), "r"(v.x), "r"(v.y), "r"(v.z), "r"(v.w) : "memory");
}
__device__ __forceinline__ void cpasync16(uint32_t dst, const void* src) {
    asm volatile("cp.async.cg.shared.global [%0], [%1], 16;" :: "r"(dst), "l"(src) : "memory");
}
#define CP_COMMIT() asm volatile("cp.async.commit_group;" ::: "memory")
#define CP_WAIT0()  asm volatile("cp.async.wait_group 0;" ::: "memory")
#define LDMX4(r, addr) \
    asm volatile("ldmatrix.sync.aligned.m8n8.x4.shared.b16 {%0,%1,%2,%3}, [%4];" \
        : "=r"((r)[0]), "=r"((r)[1]), "=r"((r)[2]), "=r"((r)[3]) : "r"(addr))
__device__ __forceinline__ void mma16816(float* d, const uint32_t* a, const uint32_t* b) {
    asm volatile(
        "mma.sync.aligned.m16n8k16.row.col.f32.bf16.bf16.f32 "
        "{%0,%1,%2,%3}, {%4,%5,%6,%7}, {%8,%9}, {%0,%1,%2,%3};"
        : "+f"(d[0]), "+f"(d[1]), "+f"(d[2]), "+f"(d[3])
        : "r"(a[0]), "r"(a[1]), "r"(a[2]), "r"(a[3]), "r"(b[0]), "r"(b[1]));
}
__device__ __forceinline__ uint32_t packbf(float a, float b) {
    __nv_bfloat162 t = __floats2bfloat162_rn(a, b);
    return *reinterpret_cast<uint32_t*>(&t);
}

// ---------------------------------------------------------------------------
// Weight prep: fp32 [k][n] -> bf16 hi/lo, transposed to [n][k] row-major
// ---------------------------------------------------------------------------
__global__ void prep_w(const float* __restrict__ w0, const float* __restrict__ w1,
                       const float* __restrict__ w2, const float* __restrict__ w3)
{
    const float* ws[4] = {w0, w1, w2, w3};
    const float* w = ws[blockIdx.x];
    char* bh = (char*)g_Bhi[blockIdx.x];
    char* bl = (char*)g_Blo[blockIdx.x];
    for (int c = threadIdx.x; c < DIM * DIM / 8; c += blockDim.x) {
        const int n = c >> 4;
        const int k0 = (c & 15) * 8;
        float v[8], lf[8];
        #pragma unroll
        for (int j = 0; j < 8; j++) v[j] = w[(k0 + j) * DIM + n];
        #pragma unroll
        for (int j = 0; j < 8; j++)
            lf[j] = v[j] - __bfloat162float(__float2bfloat16_rn(v[j]));
        uint4 hp, lp;
        hp.x = packbf(v[0], v[1]); hp.y = packbf(v[2], v[3]);
        hp.z = packbf(v[4], v[5]); hp.w = packbf(v[6], v[7]);
        lp.x = packbf(lf[0], lf[1]); lp.y = packbf(lf[2], lf[3]);
        lp.z = packbf(lf[4], lf[5]); lp.w = packbf(lf[6], lf[7]);
        const uint32_t off = (uint32_t)(n * DIM + k0) * 2;
        *(uint4*)(bh + off) = hp;
        *(uint4*)(bl + off) = lp;
    }
}

// ---------------------------------------------------------------------------
// Stage kernel: 64-token tile, 2 CTAs/SM. cp.async B-image, A build, split GEMM.
// mode 0 = encoder (in = x), mode 1 = gc (band_agg + relu)
// ---------------------------------------------------------------------------
__global__ __launch_bounds__(256, 2)
void stage_kernel(const float* __restrict__ in,
                  const __nv_bfloat16* __restrict__ Bhi_g,
                  const __nv_bfloat16* __restrict__ Blo_g,
                  const float* __restrict__ bias,
                  const float* __restrict__ w1, const float* __restrict__ b1,
                  float* __restrict__ out, int mode)
{
    extern __shared__ float sm[];
    const int tid = threadIdx.x;
    const int wid = tid >> 5, lid = tid & 31;
    const uint32_t smb = smem_u32(sm);
    const uint32_t AhiS = smb + 4096;
    const uint32_t AloS = AhiS + TOK * RSB;          // 17408 each
    const uint32_t BhiS = AloS + TOK * RSB;
    const uint32_t BloS = BhiS + DIM * RSB;          // 34816 each
    const int token0 = blockIdx.x * TOK;

    // async copy of B images (overlaps the A-build below)
    {
        const char* sh = (const char*)Bhi_g;
        const char* sl = (const char*)Blo_g;
        #pragma unroll
        for (int it = 0; it < 8; it++) {
            const int i = tid + it * 256;   // 2048 chunks of 16B
            const uint32_t dst = (uint32_t)((i >> 4) * RSB + (i & 15) * 16);
            cpasync16(BhiS + dst, sh + i * 16);
            cpasync16(BloS + dst, sl + i * 16);
        }
        CP_COMMIT();
    }
    if (tid < 128) sm[tid] = bias[tid];
    if (mode == 0) {
        for (int i = tid; i < 768; i += 256) sm[128 + i] = w1[i];
        if (tid < 128) sm[896 + tid] = b1[tid];
    }

    // -------- build A (hi/lo): 4 threads per row, 32 cols each --------
    const int row = tid >> 2, q = tid & 3;
    if (mode == 1) {
        const int s = (token0 & (SEQ - 1)) + row;
        const float scale = (s == 0 || s == SEQ - 1) ? 0.5f : (1.0f / 3.0f);
        const float4* pc = (const float4*)(in + (size_t)(token0 + row) * DIM) + q * 8;
        const bool hl = (s > 0), hr = (s < SEQ - 1);
        #pragma unroll
        for (int ch = 0; ch < 4; ch++) {
            float4 c0 = pc[ch * 2], c1 = pc[ch * 2 + 1];
            float4 z = make_float4(0.f, 0.f, 0.f, 0.f);
            float4 l0 = z, l1 = z, r0 = z, r1 = z;
            if (hl) { l0 = pc[ch * 2 - 32]; l1 = pc[ch * 2 + 1 - 32]; }
            if (hr) { r0 = pc[ch * 2 + 32]; r1 = pc[ch * 2 + 1 + 32]; }
            float v[8], lf[8];
            v[0] = (c0.x + l0.x + r0.x) * scale; v[1] = (c0.y + l0.y + r0.y) * scale;
            v[2] = (c0.z + l0.z + r0.z) * scale; v[3] = (c0.w + l0.w + r0.w) * scale;
            v[4] = (c1.x + l1.x + r1.x) * scale; v[5] = (c1.y + l1.y + r1.y) * scale;
            v[6] = (c1.z + l1.z + r1.z) * scale; v[7] = (c1.w + l1.w + r1.w) * scale;
            #pragma unroll
            for (int j = 0; j < 8; j++)
                lf[j] = v[j] - __bfloat162float(__float2bfloat16_rn(v[j]));
            uint4 hp, lp;
            hp.x = packbf(v[0], v[1]); hp.y = packbf(v[2], v[3]);
            hp.z = packbf(v[4], v[5]); hp.w = packbf(v[6], v[7]);
            lp.x = packbf(lf[0], lf[1]); lp.y = packbf(lf[2], lf[3]);
            lp.z = packbf(lf[4], lf[5]); lp.w = packbf(lf[6], lf[7]);
            const int k0 = q * 32 + ch * 8;
            const uint32_t off = (uint32_t)(row * RSB + k0 * 2);
            sts128(AhiS + off, hp);
            sts128(AloS + off, lp);
        }
    } else {
        float xv[6];
        const float* xr = in + (size_t)(token0 + row) * 6;
        #pragma unroll
        for (int k = 0; k < 6; k++) xv[k] = xr[k];
        __syncthreads();   // w1/b1 header must be ready
        #pragma unroll
        for (int ch = 0; ch < 4; ch++) {
            const int k0 = q * 32 + ch * 8;
            float v[8], lf[8];
            #pragma unroll
            for (int j = 0; j < 8; j++) {
                const int c = k0 + j;
                float a = sm[896 + c];
                #pragma unroll
                for (int k = 0; k < 6; k++) a += xv[k] * sm[128 + k * 128 + c];
                v[j] = fmaxf(a, 0.f);
                lf[j] = v[j] - __bfloat162float(__float2bfloat16_rn(v[j]));
            }
            uint4 hp, lp;
            hp.x = packbf(v[0], v[1]); hp.y = packbf(v[2], v[3]);
            hp.z = packbf(v[4], v[5]); hp.w = packbf(v[6], v[7]);
            lp.x = packbf(lf[0], lf[1]); lp.y = packbf(lf[2], lf[3]);
            lp.z = packbf(lf[4], lf[5]); lp.w = packbf(lf[6], lf[7]);
            const uint32_t off = (uint32_t)(row * RSB + k0 * 2);
            sts128(AhiS + off, hp);
            sts128(AloS + off, lp);
        }
    }
    CP_WAIT0();
    __syncthreads();

    // -------- warp-level split GEMM: warp (wm, wn) owns rows wm*32+, cols wn*32+ --------
    const int wm = wid & 1, wn = wid >> 1;
    const int g = lid >> 2, t = lid & 3;

    float acc[2][4][4];
    #pragma unroll
    for (int mi = 0; mi < 2; mi++)
        #pragma unroll
        for (int ni = 0; ni < 4; ni++)
            #pragma unroll
            for (int j = 0; j < 4; j++) acc[mi][ni][j] = 0.f;

    // per-lane ldmatrix source offsets
    const uint32_t aoffl = (uint32_t)((((lid >> 3) & 1) * 8 + (lid & 7)) * RSB + (lid >> 4) * 16);
    const uint32_t boffl = (uint32_t)((((lid >> 4) * 8) + (lid & 7)) * RSB + ((lid >> 3) & 1) * 16);
    const uint32_t aBase = (uint32_t)(wm * 32) * RSB + aoffl;
    const uint32_t bBase = (uint32_t)(wn * 32) * RSB + boffl;

    #pragma unroll
    for (int ks = 0; ks < 8; ks++) {
        const uint32_t kb = ks * 32;
        uint32_t ah[2][4], al[2][4];
        LDMX4(ah[0], AhiS + aBase + kb);
        LDMX4(ah[1], AhiS + aBase + 16 * RSB + kb);
        LDMX4(al[0], AloS + aBase + kb);
        LDMX4(al[1], AloS + aBase + 16 * RSB + kb);
        uint32_t bh[2][4], bl[2][4];
        #pragma unroll
        for (int p = 0; p < 2; p++) {
            LDMX4(bh[p], BhiS + bBase + (uint32_t)(p * 16) * RSB + kb);
            LDMX4(bl[p], BloS + bBase + (uint32_t)(p * 16) * RSB + kb);
        }
        #pragma unroll
        for (int p = 0; p < 2; p++) {
            #pragma unroll
            for (int hn = 0; hn < 2; hn++) {
                const int ni = p * 2 + hn;
                #pragma unroll
                for (int mi = 0; mi < 2; mi++) {
                    mma16816(acc[mi][ni], ah[mi], &bh[p][hn * 2]);
                    mma16816(acc[mi][ni], al[mi], &bh[p][hn * 2]);
                    mma16816(acc[mi][ni], ah[mi], &bl[p][hn * 2]);
                }
            }
        }
    }

    // -------- epilogue: bias (+relu), float2 stores --------
    const bool relu = (mode == 1);
    #pragma unroll
    for (int mi = 0; mi < 2; mi++) {
        const int r0 = token0 + wm * 32 + mi * 16 + g;
        #pragma unroll
        for (int ni = 0; ni < 4; ni++) {
            const int col = wn * 32 + ni * 8 + 2 * t;
            const float bx = sm[col], by = sm[col + 1];
            float2 v0, v1;
            v0.x = acc[mi][ni][0] + bx; v0.y = acc[mi][ni][1] + by;
            v1.x = acc[mi][ni][2] + bx; v1.y = acc[mi][ni][3] + by;
            if (relu) {
                v0.x = fmaxf(v0.x, 0.f); v0.y = fmaxf(v0.y, 0.f);
                v1.x = fmaxf(v1.x, 0.f); v1.y = fmaxf(v1.y, 0.f);
            }
            *(float2*)(out + (size_t)r0 * DIM + col) = v0;
            *(float2*)(out + (size_t)(r0 + 8) * DIM + col) = v1;
        }
    }
}

// ---------------------------------------------------------------------------
// Pool partials + classifier
// ---------------------------------------------------------------------------
__global__ __launch_bounds__(128) void pool_part_kernel(const float* __restrict__ h)
{
    const int b = blockIdx.x >> 3, j = blockIdx.x & 7;
    const int tid = threadIdx.x;
    const float* base = h + ((size_t)b * SEQ + j * 256) * DIM;
    float s = 0.f;
    #pragma unroll 8
    for (int r = 0; r < 256; r++) s += base[(size_t)r * DIM + tid];
    g_part[blockIdx.x * DIM + tid] = s;
}

__global__ __launch_bounds__(128) void cls_kernel(
    const float* __restrict__ w1, const float* __restrict__ b1,
    const float* __restrict__ w2, const float* __restrict__ b2,
    float* __restrict__ out)
{
    __shared__ float P[128];
    __shared__ float C1[64];
    const int b = blockIdx.x, tid = threadIdx.x;
    float s = 0.f;
    #pragma unroll
    for (int j = 0; j < 8; j++) s += g_part[(b * 8 + j) * DIM + tid];
    P[tid] = s * (1.0f / (float)SEQ);
    __syncthreads();
    if (tid < 64) {
        float a = b1[tid];
        #pragma unroll 8
        for (int k = 0; k < 128; k++) a += P[k] * w1[k * 64 + tid];
        C1[tid] = fmaxf(a, 0.f);
    }
    __syncthreads();
    if (tid < 3) {
        float a = b2[tid];
        #pragma unroll
        for (int k = 0; k < 64; k++) a += C1[k] * w2[k * 3 + tid];
        out[b * 3 + tid] = a;
    }
}

extern "C" void kernel_launch(void* const* d_in, const int* in_sizes, int n_in,
                              void* d_out, int out_size)
{
    const float* x      = (const float*)d_in[0];
    const float* enc_w1 = (const float*)d_in[1];
    const float* enc_b1 = (const float*)d_in[2];
    const float* enc_w2 = (const float*)d_in[3];
    const float* enc_b2 = (const float*)d_in[4];
    const float* gc1_w  = (const float*)d_in[5];
    const float* gc1_b  = (const float*)d_in[6];
    const float* gc2_w  = (const float*)d_in[7];
    const float* gc2_b  = (const float*)d_in[8];
    const float* gc3_w  = (const float*)d_in[9];
    const float* gc3_b  = (const float*)d_in[10];
    const float* cls_w1 = (const float*)d_in[11];
    const float* cls_b1 = (const float*)d_in[12];
    const float* cls_w2 = (const float*)d_in[13];
    const float* cls_b2 = (const float*)d_in[14];
    float* out = (float*)d_out;

    void *p0, *p1, *pbh, *pbl;
    cudaGetSymbolAddress(&p0, g_h0);
    cudaGetSymbolAddress(&p1, g_h1);
    cudaGetSymbolAddress(&pbh, g_Bhi);
    cudaGetSymbolAddress(&pbl, g_Blo);
    float* h0 = (float*)p0;
    float* h1 = (float*)p1;
    const __nv_bfloat16* Bhi = (const __nv_bfloat16*)pbh;
    const __nv_bfloat16* Blo = (const __nv_bfloat16*)pbl;

    const size_t stage_sm = 4096 + 2 * (size_t)TOK * RSB + 2 * (size_t)DIM * RSB;  // 106KB
    cudaFuncSetAttribute(stage_kernel, cudaFuncAttributeMaxDynamicSharedMemorySize, (int)stage_sm);
    cudaFuncSetAttribute(stage_kernel, cudaFuncAttributePreferredSharedMemoryCarveout, 100);

    prep_w<<<4, 256>>>(enc_w2, gc1_w, gc2_w, gc3_w);

    const int nblk = NTOK / TOK;   // 1024
    stage_kernel<<<nblk, 256, stage_sm>>>(x,  Bhi + 0 * DIM * DIM, Blo + 0 * DIM * DIM, enc_b2, enc_w1, enc_b1, h0, 0);
    stage_kernel<<<nblk, 256, stage_sm>>>(h0, Bhi + 1 * DIM * DIM, Blo + 1 * DIM * DIM, gc1_b,  enc_w1, enc_b1, h1, 1);
    stage_kernel<<<nblk, 256, stage_sm>>>(h1, Bhi + 2 * DIM * DIM, Blo + 2 * DIM * DIM, gc2_b,  enc_w1, enc_b1, h0, 1);
    stage_kernel<<<nblk, 256, stage_sm>>>(h0, Bhi + 3 * DIM * DIM, Blo + 3 * DIM * DIM, gc3_b,  enc_w1, enc_b1, h1, 1);
    pool_part_kernel<<<NB * 8, 128>>>(h1);
    cls_kernel<<<NB, 128>>>(cls_w1, cls_b1, cls_w2, cls_b2, out);
}

// round 6
// speedup vs baseline: 1.6046x; 1.6046x over previous
#include <cuda_runtime.h>
#include <cuda_fp16.h>
#include <cstdint>

#define SEQ 2048
#define NB  32
#define DIM 128
#define NTOK (NB*SEQ)
#define TOK 64

// ---------------- scratch (no allocations allowed) ----------------
__device__ __align__(16) __half g_h0[NTOK*DIM];
__device__ __align__(16) __half g_h1[NTOK*DIM];
__device__ float g_part[NB*8*DIM];
// prepared weight images: fp16 hi / scaled-lo, [n][k], 16B-chunk swizzle baked
__device__ __align__(16) __half g_Whi[4][DIM*DIM];
__device__ __align__(16) __half g_Wlo[4][DIM*DIM];

// ---------------- helpers ----------------
__device__ __forceinline__ uint32_t smem_u32(const void* p) {
    uint32_t a;
    asm("{ .reg .u64 t; cvta.to.shared.u64 t, %1; cvt.u32.u64 %0, t; }" : "=r"(a) : "l"(p));
    return a;
}
__device__ __forceinline__ void sts128(uint32_t addr, uint4 v) {
    asm volatile("st.shared.v4.b32 [%0], {%1,%2,%3,%4};" :: "r"(addr), "r"(v.x), "r"(v.y), "r"(v.z), "r"(v.w) : "memory");
}
__device__ __forceinline__ uint4 lds128(uint32_t addr) {
    uint4 v;
    asm volatile("ld.shared.v4.b32 {%0,%1,%2,%3}, [%4];"
        : "=r"(v.x), "=r"(v.y), "=r"(v.z), "=r"(v.w) : "r"(addr));
    return v;
}
__device__ __forceinline__ void cpasync16(uint32_t dst, const void* src) {
    asm volatile("cp.async.cg.shared.global [%0], [%1], 16;" :: "r"(dst), "l"(src) : "memory");
}
#define CP_COMMIT() asm volatile("cp.async.commit_group;" ::: "memory")
#define CP_WAIT0()  asm volatile("cp.async.wait_group 0;" ::: "memory")
#define LDMX4(r, addr) \
    asm volatile("ldmatrix.sync.aligned.m8n8.x4.shared.b16 {%0,%1,%2,%3}, [%4];" \
        : "=r"((r)[0]), "=r"((r)[1]), "=r"((r)[2]), "=r"((r)[3]) : "r"(addr))
__device__ __forceinline__ void mma16816(float* d, const uint32_t* a, const uint32_t* b) {
    asm volatile(
        "mma.sync.aligned.m16n8k16.row.col.f32.f16.f16.f32 "
        "{%0,%1,%2,%3}, {%4,%5,%6,%7}, {%8,%9}, {%0,%1,%2,%3};"
        : "+f"(d[0]), "+f"(d[1]), "+f"(d[2]), "+f"(d[3])
        : "r"(a[0]), "r"(a[1]), "r"(a[2]), "r"(a[3]), "r"(b[0]), "r"(b[1]));
}
// swizzled byte offset inside a [rows][128 fp16] tile: 256B rows, 16B chunks
__device__ __forceinline__ uint32_t tswz(int row, int kchunk) {
    return (uint32_t)(row * 256 + ((kchunk ^ (row & 7)) << 4));
}
__device__ __forceinline__ uint32_t packh(float a, float b) {
    __half2 t = __floats2half2_rn(a, b);
    return *reinterpret_cast<uint32_t*>(&t);
}

// ---------------------------------------------------------------------------
// Weight prep: fp32 [k][n] -> fp16 hi + fp16 lo*2^10, [n][k], swizzle baked
// ---------------------------------------------------------------------------
__global__ void prep_w(const float* __restrict__ w0, const float* __restrict__ w1,
                       const float* __restrict__ w2, const float* __restrict__ w3)
{
    const float* ws[4] = {w0, w1, w2, w3};
    const float* w = ws[blockIdx.x];
    __half* bh = g_Whi[blockIdx.x];
    __half* bl = g_Wlo[blockIdx.x];
    for (int c = threadIdx.x; c < 2048; c += blockDim.x) {
        const int n = c >> 4, kc = c & 15, k0 = kc * 8;
        const int base = n * 128 + ((kc ^ (n & 7)) << 3);
        #pragma unroll
        for (int j = 0; j < 8; j++) {
            const float v = w[(k0 + j) * DIM + n];
            const __half hi = __float2half_rn(v);
            bh[base + j] = hi;
            bl[base + j] = __float2half_rn((v - __half2float(hi)) * 1024.0f);
        }
    }
}

// ---------------------------------------------------------------------------
// Stage kernel: 64-token tile. cp.async B + raw tile, A build, 2-product GEMM.
// mode 0 = encoder (in = x fp32), mode 1 = gc (in = h fp16, band_agg + relu)
// ---------------------------------------------------------------------------
__global__ __launch_bounds__(256, 2)
void stage_kernel(const void* __restrict__ in_v,
                  const __half* __restrict__ Whi_g,
                  const __half* __restrict__ Wlo_g,
                  const float* __restrict__ bias,
                  const float* __restrict__ w1, const float* __restrict__ b1,
                  __half* __restrict__ out, int mode)
{
    extern __shared__ float sm[];
    const int tid = threadIdx.x;
    const int wid = tid >> 5, lid = tid & 31;
    const uint32_t smb = smem_u32(sm);
    const uint32_t AS   = smb + 4096;        // 16KB  (64 x 256B)
    const uint32_t BhS  = AS + 16384;        // 32KB  (128 x 256B)
    const uint32_t BlS  = BhS + 32768;       // 32KB
    const uint32_t rawS = BlS + 32768;       // 16.9KB (66 x 256B)
    const int token0 = blockIdx.x * TOK;
    const int s0 = token0 & (SEQ - 1);
    const int batch_base = token0 - s0;

    // async copy of B hi/lo images (pre-swizzled, linear)
    {
        const char* sh = (const char*)Whi_g;
        const char* sl = (const char*)Wlo_g;
        #pragma unroll
        for (int it = 0; it < 8; it++) {
            const int i = tid + it * 256;
            cpasync16(BhS + i * 16, sh + i * 16);
            cpasync16(BlS + i * 16, sl + i * 16);
        }
    }
    // async copy of raw activation tile (66 halo rows) for gc mode
    if (mode == 1) {
        const __half* hin = (const __half*)in_v;
        for (int i = tid; i < 66 * 16; i += 256) {
            const int row = i >> 4, c = i & 15;
            const int s = s0 - 1 + row;
            const uint32_t dst = rawS + tswz(row, c);
            if (s >= 0 && s < SEQ) {
                cpasync16(dst, hin + (size_t)(batch_base + s) * DIM + c * 8);
            } else {
                sts128(dst, make_uint4(0, 0, 0, 0));
            }
        }
    }
    CP_COMMIT();

    if (tid < 128) sm[tid] = bias[tid];
    if (mode == 0) {
        for (int i = tid; i < 768; i += 256) sm[128 + i] = w1[i];
        if (tid < 128) sm[896 + tid] = b1[tid];
    }

    CP_WAIT0();
    __syncthreads();

    // -------- build A fp16 tile (64 x 128), swizzled --------
    const int r = tid >> 2, q = tid & 3;
    if (mode == 1) {
        const int s_out = s0 + r;
        const float scale = (s_out == 0 || s_out == SEQ - 1) ? 0.5f : (1.0f / 3.0f);
        #pragma unroll
        for (int ch = 0; ch < 4; ch++) {
            const int c = q * 4 + ch;
            const uint4 u0 = lds128(rawS + tswz(r,     c));
            const uint4 u1 = lds128(rawS + tswz(r + 1, c));
            const uint4 u2 = lds128(rawS + tswz(r + 2, c));
            uint4 o;
            const uint32_t* p0 = &u0.x;
            const uint32_t* p1 = &u1.x;
            const uint32_t* p2 = &u2.x;
            uint32_t* po = &o.x;
            #pragma unroll
            for (int wd = 0; wd < 4; wd++) {
                float2 f0 = __half22float2(*(const __half2*)&p0[wd]);
                float2 f1 = __half22float2(*(const __half2*)&p1[wd]);
                float2 f2 = __half22float2(*(const __half2*)&p2[wd]);
                po[wd] = packh((f0.x + f1.x + f2.x) * scale,
                               (f0.y + f1.y + f2.y) * scale);
            }
            sts128(AS + tswz(r, c), o);
        }
    } else {
        const float* x = (const float*)in_v;
        float xv[6];
        const float* xr = x + (size_t)(token0 + r) * 6;
        #pragma unroll
        for (int k = 0; k < 6; k++) xv[k] = xr[k];
        #pragma unroll
        for (int ch = 0; ch < 4; ch++) {
            const int c = q * 4 + ch;
            const int k0 = c * 8;
            uint4 o;
            uint32_t* po = &o.x;
            #pragma unroll
            for (int wd = 0; wd < 4; wd++) {
                float v0, v1;
                {
                    const int cc = k0 + wd * 2;
                    float a = sm[896 + cc];
                    #pragma unroll
                    for (int k = 0; k < 6; k++) a += xv[k] * sm[128 + k * 128 + cc];
                    v0 = fmaxf(a, 0.f);
                }
                {
                    const int cc = k0 + wd * 2 + 1;
                    float a = sm[896 + cc];
                    #pragma unroll
                    for (int k = 0; k < 6; k++) a += xv[k] * sm[128 + k * 128 + cc];
                    v1 = fmaxf(a, 0.f);
                }
                po[wd] = packh(v0, v1);
            }
            sts128(AS + tswz(r, c), o);
        }
    }
    __syncthreads();

    // -------- warp-level 2-product GEMM: warp (wm, wn): rows wm*32+, cols wn*32+ --------
    const int wm = wid & 1, wn = wid >> 1;
    const int g = lid >> 2, t = lid & 3;

    float acc1[2][4][4], acc2[2][4][4];
    #pragma unroll
    for (int mi = 0; mi < 2; mi++)
        #pragma unroll
        for (int ni = 0; ni < 4; ni++)
            #pragma unroll
            for (int j = 0; j < 4; j++) { acc1[mi][ni][j] = 0.f; acc2[mi][ni][j] = 0.f; }

    // per-lane ldmatrix rows
    const int arowl = ((lid >> 3) & 1) * 8 + (lid & 7);  // + mi*16 + wm*32
    const int akcl  = lid >> 4;                           // kchunk low bit
    const int browl = (lid >> 4) * 8 + (lid & 7);         // + p*16 + wn*32
    const int bkcl  = (lid >> 3) & 1;

    #pragma unroll
    for (int ks = 0; ks < 8; ks++) {
        uint32_t ah[2][4];
        #pragma unroll
        for (int mi = 0; mi < 2; mi++) {
            const int row = wm * 32 + mi * 16 + arowl;
            LDMX4(ah[mi], AS + tswz(row, ks * 2 + akcl));
        }
        #pragma unroll
        for (int p = 0; p < 2; p++) {
            const int nrow = wn * 32 + p * 16 + browl;
            const uint32_t boff = tswz(nrow, ks * 2 + bkcl);
            uint32_t bh[4], bl[4];
            LDMX4(bh, BhS + boff);
            LDMX4(bl, BlS + boff);
            #pragma unroll
            for (int hn = 0; hn < 2; hn++) {
                const int ni = p * 2 + hn;
                #pragma unroll
                for (int mi = 0; mi < 2; mi++) {
                    mma16816(acc1[mi][ni], ah[mi], &bh[hn * 2]);
                    mma16816(acc2[mi][ni], ah[mi], &bl[hn * 2]);
                }
            }
        }
    }

    // -------- epilogue: D = D1 + D2/1024 + bias, (+relu), fp16 stores --------
    const bool relu = (mode == 1);
    const float INV = 1.0f / 1024.0f;
    #pragma unroll
    for (int mi = 0; mi < 2; mi++) {
        const int r0 = token0 + wm * 32 + mi * 16 + g;
        #pragma unroll
        for (int ni = 0; ni < 4; ni++) {
            const int col = wn * 32 + ni * 8 + 2 * t;
            const float bx = sm[col], by = sm[col + 1];
            float c0 = acc1[mi][ni][0] + acc2[mi][ni][0] * INV + bx;
            float c1 = acc1[mi][ni][1] + acc2[mi][ni][1] * INV + by;
            float c2 = acc1[mi][ni][2] + acc2[mi][ni][2] * INV + bx;
            float c3 = acc1[mi][ni][3] + acc2[mi][ni][3] * INV + by;
            if (relu) {
                c0 = fmaxf(c0, 0.f); c1 = fmaxf(c1, 0.f);
                c2 = fmaxf(c2, 0.f); c3 = fmaxf(c3, 0.f);
            }
            *(__half2*)(out + (size_t)r0 * DIM + col) = __floats2half2_rn(c0, c1);
            *(__half2*)(out + (size_t)(r0 + 8) * DIM + col) = __floats2half2_rn(c2, c3);
        }
    }
}

// ---------------------------------------------------------------------------
// Pool partials + classifier
// ---------------------------------------------------------------------------
__global__ __launch_bounds__(128) void pool_part_kernel(const __half* __restrict__ h)
{
    const int b = blockIdx.x >> 3, j = blockIdx.x & 7;
    const int tid = threadIdx.x;
    const __half* base = h + ((size_t)b * SEQ + j * 256) * DIM;
    float s = 0.f;
    #pragma unroll 8
    for (int r = 0; r < 256; r++) s += __half2float(base[(size_t)r * DIM + tid]);
    g_part[blockIdx.x * DIM + tid] = s;
}

__global__ __launch_bounds__(128) void cls_kernel(
    const float* __restrict__ w1, const float* __restrict__ b1,
    const float* __restrict__ w2, const float* __restrict__ b2,
    float* __restrict__ out)
{
    __shared__ float P[128];
    __shared__ float C1[64];
    const int b = blockIdx.x, tid = threadIdx.x;
    float s = 0.f;
    #pragma unroll
    for (int j = 0; j < 8; j++) s += g_part[(b * 8 + j) * DIM + tid];
    P[tid] = s * (1.0f / (float)SEQ);
    __syncthreads();
    if (tid < 64) {
        float a = b1[tid];
        #pragma unroll 8
        for (int k = 0; k < 128; k++) a += P[k] * w1[k * 64 + tid];
        C1[tid] = fmaxf(a, 0.f);
    }
    __syncthreads();
    if (tid < 3) {
        float a = b2[tid];
        #pragma unroll
        for (int k = 0; k < 64; k++) a += C1[k] * w2[k * 3 + tid];
        out[b * 3 + tid] = a;
    }
}

extern "C" void kernel_launch(void* const* d_in, const int* in_sizes, int n_in,
                              void* d_out, int out_size)
{
    const float* x      = (const float*)d_in[0];
    const float* enc_w1 = (const float*)d_in[1];
    const float* enc_b1 = (const float*)d_in[2];
    const float* enc_w2 = (const float*)d_in[3];
    const float* enc_b2 = (const float*)d_in[4];
    const float* gc1_w  = (const float*)d_in[5];
    const float* gc1_b  = (const float*)d_in[6];
    const float* gc2_w  = (const float*)d_in[7];
    const float* gc2_b  = (const float*)d_in[8];
    const float* gc3_w  = (const float*)d_in[9];
    const float* gc3_b  = (const float*)d_in[10];
    const float* cls_w1 = (const float*)d_in[11];
    const float* cls_b1 = (const float*)d_in[12];
    const float* cls_w2 = (const float*)d_in[13];
    const float* cls_b2 = (const float*)d_in[14];
    float* out = (float*)d_out;

    void *p0, *p1, *pwh, *pwl;
    cudaGetSymbolAddress(&p0, g_h0);
    cudaGetSymbolAddress(&p1, g_h1);
    cudaGetSymbolAddress(&pwh, g_Whi);
    cudaGetSymbolAddress(&pwl, g_Wlo);
    __half* h0 = (__half*)p0;
    __half* h1 = (__half*)p1;
    const __half* Whi = (const __half*)pwh;
    const __half* Wlo = (const __half*)pwl;

    const size_t stage_sm = 4096 + 16384 + 32768 + 32768 + 66 * 256;  // 102912 B
    cudaFuncSetAttribute(stage_kernel, cudaFuncAttributeMaxDynamicSharedMemorySize, (int)stage_sm);
    cudaFuncSetAttribute(stage_kernel, cudaFuncAttributePreferredSharedMemoryCarveout, 100);

    prep_w<<<4, 256>>>(enc_w2, gc1_w, gc2_w, gc3_w);

    const int nblk = NTOK / TOK;   // 1024
    stage_kernel<<<nblk, 256, stage_sm>>>(x,  Whi + 0 * DIM * DIM, Wlo + 0 * DIM * DIM, enc_b2, enc_w1, enc_b1, h0, 0);
    stage_kernel<<<nblk, 256, stage_sm>>>(h0, Whi + 1 * DIM * DIM, Wlo + 1 * DIM * DIM, gc1_b,  enc_w1, enc_b1, h1, 1);
    stage_kernel<<<nblk, 256, stage_sm>>>(h1, Whi + 2 * DIM * DIM, Wlo + 2 * DIM * DIM, gc2_b,  enc_w1, enc_b1, h0, 1);
    stage_kernel<<<nblk, 256, stage_sm>>>(h0, Whi + 3 * DIM * DIM, Wlo + 3 * DIM * DIM, gc3_b,  enc_w1, enc_b1, h1, 1);
    pool_part_kernel<<<NB * 8, 128>>>(h1);
    cls_kernel<<<NB, 128>>>(cls_w1, cls_b1, cls_w2, cls_b2, out);
}

// round 7
// speedup vs baseline: 1.8811x; 1.1724x over previous
#include <cuda_runtime.h>
#include <cuda_fp16.h>
#include <cstdint>

#define SEQ 2048
#define NB  32
#define DIM 128
#define NTOK (NB*SEQ)
#define TOK 64
#define NTILES (NTOK/TOK)      // 1024
#define GRID 296               // 2 CTAs per SM, persistent

// ---------------- scratch (no allocations allowed) ----------------
__device__ __align__(16) __half g_h0[NTOK*DIM];
__device__ __align__(16) __half g_h1[NTOK*DIM];
__device__ float g_part[NB*DIM];
// prepared weight images: fp16 hi / scaled-lo, [n][k], 16B-chunk swizzle baked
__device__ __align__(16) __half g_Whi[4][DIM*DIM];
__device__ __align__(16) __half g_Wlo[4][DIM*DIM];

// ---------------- helpers ----------------
__device__ __forceinline__ uint32_t smem_u32(const void* p) {
    uint32_t a;
    asm("{ .reg .u64 t; cvta.to.shared.u64 t, %1; cvt.u32.u64 %0, t; }" : "=r"(a) : "l"(p));
    return a;
}
__device__ __forceinline__ void sts128(uint32_t addr, uint4 v) {
    asm volatile("st.shared.v4.b32 [%0], {%1,%2,%3,%4};" :: "r"(addr), "r"(v.x), "r"(v.y), "r"(v.z), "r"(v.w) : "memory");
}
__device__ __forceinline__ uint4 lds128(uint32_t addr) {
    uint4 v;
    asm volatile("ld.shared.v4.b32 {%0,%1,%2,%3}, [%4];"
        : "=r"(v.x), "=r"(v.y), "=r"(v.z), "=r"(v.w) : "r"(addr));
    return v;
}
__device__ __forceinline__ void cpasync16(uint32_t dst, const void* src) {
    asm volatile("cp.async.cg.shared.global [%0], [%1], 16;" :: "r"(dst), "l"(src) : "memory");
}
#define CP_COMMIT() asm volatile("cp.async.commit_group;" ::: "memory")
#define CP_WAIT0()  asm volatile("cp.async.wait_group 0;" ::: "memory")
#define LDMX4(r, addr) \
    asm volatile("ldmatrix.sync.aligned.m8n8.x4.shared.b16 {%0,%1,%2,%3}, [%4];" \
        : "=r"((r)[0]), "=r"((r)[1]), "=r"((r)[2]), "=r"((r)[3]) : "r"(addr))
__device__ __forceinline__ void mma16816(float* d, const uint32_t* a, const uint32_t* b) {
    asm volatile(
        "mma.sync.aligned.m16n8k16.row.col.f32.f16.f16.f32 "
        "{%0,%1,%2,%3}, {%4,%5,%6,%7}, {%8,%9}, {%0,%1,%2,%3};"
        : "+f"(d[0]), "+f"(d[1]), "+f"(d[2]), "+f"(d[3])
        : "r"(a[0]), "r"(a[1]), "r"(a[2]), "r"(a[3]), "r"(b[0]), "r"(b[1]));
}
// swizzled byte offset inside a [rows][128 fp16] tile: 256B rows, 16B chunks
__device__ __forceinline__ uint32_t tswz(int row, int kchunk) {
    return (uint32_t)(row * 256 + ((kchunk ^ (row & 7)) << 4));
}
__device__ __forceinline__ uint32_t packh(float a, float b) {
    __half2 t = __floats2half2_rn(a, b);
    return *reinterpret_cast<uint32_t*>(&t);
}

// ---------------------------------------------------------------------------
// Weight prep: fp32 [k][n] -> fp16 hi + fp16 lo*2^10, [n][k], swizzle baked
// ---------------------------------------------------------------------------
__global__ void prep_w(const float* __restrict__ w0, const float* __restrict__ w1,
                       const float* __restrict__ w2, const float* __restrict__ w3)
{
    const float* ws[4] = {w0, w1, w2, w3};
    const float* w = ws[blockIdx.x];
    __half* bh = g_Whi[blockIdx.x];
    __half* bl = g_Wlo[blockIdx.x];
    for (int c = threadIdx.x; c < 2048; c += blockDim.x) {
        const int n = c >> 4, kc = c & 15, k0 = kc * 8;
        const int base = n * 128 + ((kc ^ (n & 7)) << 3);
        #pragma unroll
        for (int j = 0; j < 8; j++) {
            const float v = w[(k0 + j) * DIM + n];
            const __half hi = __float2half_rn(v);
            bh[base + j] = hi;
            bl[base + j] = __float2half_rn((v - __half2float(hi)) * 1024.0f);
        }
    }
}

__global__ void zero_part() {
    const int i = blockIdx.x * 256 + threadIdx.x;
    if (i < NB * DIM) g_part[i] = 0.f;
}

// ---------------------------------------------------------------------------
// Persistent stage kernel: B images resident, loop over token tiles with
// cp.async prefetch of the next raw tile overlapping MMA of the current.
// mode 0 = encoder (in = x fp32), mode 1 = gc (band_agg + relu + store)
// mode 2 = gc + fused mean-pool (no store)
// ---------------------------------------------------------------------------
__global__ __launch_bounds__(256, 2)
void stage_kernel(const void* __restrict__ in_v,
                  const __half* __restrict__ Whi_g,
                  const __half* __restrict__ Wlo_g,
                  const float* __restrict__ bias,
                  const float* __restrict__ w1, const float* __restrict__ b1,
                  __half* __restrict__ out, int mode)
{
    extern __shared__ float sm[];
    const int tid = threadIdx.x;
    const int wid = tid >> 5, lid = tid & 31;
    const uint32_t smb = smem_u32(sm);
    const uint32_t AS   = smb + 4096;        // 16KB  (64 x 256B)
    const uint32_t BhS  = AS + 16384;        // 32KB  (128 x 256B)
    const uint32_t BlS  = BhS + 32768;       // 32KB
    const uint32_t rawS = BlS + 32768;       // 16.9KB (66 x 256B)

    // ---- prologue: B hi/lo images + first raw tile ----
    {
        const char* sh = (const char*)Whi_g;
        const char* sl = (const char*)Wlo_g;
        #pragma unroll
        for (int it = 0; it < 8; it++) {
            const int i = tid + it * 256;
            cpasync16(BhS + i * 16, sh + i * 16);
            cpasync16(BlS + i * 16, sl + i * 16);
        }
    }
    if (mode != 0) {
        const __half* hin = (const __half*)in_v;
        const int t0 = blockIdx.x;
        const int tok0 = t0 * TOK, s0 = tok0 & (SEQ - 1), bb = tok0 - s0;
        for (int i = tid; i < 66 * 16; i += 256) {
            const int row = i >> 4, c = i & 15;
            const int s = s0 - 1 + row;
            const uint32_t dst = rawS + tswz(row, c);
            if (s >= 0 && s < SEQ) cpasync16(dst, hin + (size_t)(bb + s) * DIM + c * 8);
            else                   sts128(dst, make_uint4(0, 0, 0, 0));
        }
    }
    CP_COMMIT();

    if (tid < 128) sm[tid] = bias[tid];
    if (mode == 0) {
        for (int i = tid; i < 768; i += 256) sm[128 + i] = w1[i];
        if (tid < 128) sm[896 + tid] = b1[tid];
    }
    CP_WAIT0();
    __syncthreads();

    const int r = tid >> 2, q = tid & 3;
    const int wm = wid & 1, wn = wid >> 1;
    const int g = lid >> 2, t4 = lid & 3;
    // per-lane ldmatrix rows
    const int arowl = ((lid >> 3) & 1) * 8 + (lid & 7);
    const int akcl  = lid >> 4;
    const int browl = (lid >> 4) * 8 + (lid & 7);
    const int bkcl  = (lid >> 3) & 1;
    const float INV = 1.0f / 1024.0f;

    for (int tile = blockIdx.x; tile < NTILES; tile += GRID) {
        const int token0 = tile * TOK;
        const int s0 = token0 & (SEQ - 1);

        // ---- build A fp16 tile (64 x 128), swizzled ----
        if (mode != 0) {
            const int s_out = s0 + r;
            const float scale = (s_out == 0 || s_out == SEQ - 1) ? 0.5f : (1.0f / 3.0f);
            #pragma unroll
            for (int ch = 0; ch < 4; ch++) {
                const int c = q * 4 + ch;
                const uint4 u0 = lds128(rawS + tswz(r,     c));
                const uint4 u1 = lds128(rawS + tswz(r + 1, c));
                const uint4 u2 = lds128(rawS + tswz(r + 2, c));
                uint4 o;
                const uint32_t* p0 = &u0.x;
                const uint32_t* p1 = &u1.x;
                const uint32_t* p2 = &u2.x;
                uint32_t* po = &o.x;
                #pragma unroll
                for (int wd = 0; wd < 4; wd++) {
                    float2 f0 = __half22float2(*(const __half2*)&p0[wd]);
                    float2 f1 = __half22float2(*(const __half2*)&p1[wd]);
                    float2 f2 = __half22float2(*(const __half2*)&p2[wd]);
                    po[wd] = packh((f0.x + f1.x + f2.x) * scale,
                                   (f0.y + f1.y + f2.y) * scale);
                }
                sts128(AS + tswz(r, c), o);
            }
        } else {
            const float* x = (const float*)in_v;
            float xv[6];
            const float* xr = x + (size_t)(token0 + r) * 6;
            #pragma unroll
            for (int k = 0; k < 6; k++) xv[k] = xr[k];
            #pragma unroll
            for (int ch = 0; ch < 4; ch++) {
                const int c = q * 4 + ch;
                const int k0 = c * 8;
                uint4 o;
                uint32_t* po = &o.x;
                #pragma unroll
                for (int wd = 0; wd < 4; wd++) {
                    float v0, v1;
                    {
                        const int cc = k0 + wd * 2;
                        float a = sm[896 + cc];
                        #pragma unroll
                        for (int k = 0; k < 6; k++) a += xv[k] * sm[128 + k * 128 + cc];
                        v0 = fmaxf(a, 0.f);
                    }
                    {
                        const int cc = k0 + wd * 2 + 1;
                        float a = sm[896 + cc];
                        #pragma unroll
                        for (int k = 0; k < 6; k++) a += xv[k] * sm[128 + k * 128 + cc];
                        v1 = fmaxf(a, 0.f);
                    }
                    po[wd] = packh(v0, v1);
                }
                sts128(AS + tswz(r, c), o);
            }
        }
        __syncthreads();   // A built; raw buffer free

        // ---- prefetch next raw tile (overlaps MMA below) ----
        {
            const int tn = tile + GRID;
            if (mode != 0 && tn < NTILES) {
                const __half* hin = (const __half*)in_v;
                const int tok0n = tn * TOK, s0n = tok0n & (SEQ - 1), bbn = tok0n - s0n;
                for (int i = tid; i < 66 * 16; i += 256) {
                    const int row = i >> 4, c = i & 15;
                    const int s = s0n - 1 + row;
                    const uint32_t dst = rawS + tswz(row, c);
                    if (s >= 0 && s < SEQ) cpasync16(dst, hin + (size_t)(bbn + s) * DIM + c * 8);
                    else                   sts128(dst, make_uint4(0, 0, 0, 0));
                }
            }
            CP_COMMIT();
        }

        // ---- warp-level 2-product GEMM ----
        float acc1[2][4][4], acc2[2][4][4];
        #pragma unroll
        for (int mi = 0; mi < 2; mi++)
            #pragma unroll
            for (int ni = 0; ni < 4; ni++)
                #pragma unroll
                for (int j = 0; j < 4; j++) { acc1[mi][ni][j] = 0.f; acc2[mi][ni][j] = 0.f; }

        #pragma unroll
        for (int ks = 0; ks < 8; ks++) {
            uint32_t ah[2][4];
            #pragma unroll
            for (int mi = 0; mi < 2; mi++) {
                const int row = wm * 32 + mi * 16 + arowl;
                LDMX4(ah[mi], AS + tswz(row, ks * 2 + akcl));
            }
            #pragma unroll
            for (int p = 0; p < 2; p++) {
                const int nrow = wn * 32 + p * 16 + browl;
                const uint32_t boff = tswz(nrow, ks * 2 + bkcl);
                uint32_t bh[4], bl[4];
                LDMX4(bh, BhS + boff);
                LDMX4(bl, BlS + boff);
                #pragma unroll
                for (int hn = 0; hn < 2; hn++) {
                    const int ni = p * 2 + hn;
                    #pragma unroll
                    for (int mi = 0; mi < 2; mi++) {
                        mma16816(acc1[mi][ni], ah[mi], &bh[hn * 2]);
                        mma16816(acc2[mi][ni], ah[mi], &bl[hn * 2]);
                    }
                }
            }
        }

        // ---- epilogue ----
        if (mode == 2) {
            // fused mean-pool: relu, reduce rows in-warp, atomic partials
            const int b = token0 >> 11;
            #pragma unroll
            for (int ni = 0; ni < 4; ni++) {
                const int col = wn * 32 + ni * 8 + 2 * t4;
                const float bx = sm[col], by = sm[col + 1];
                float sx = 0.f, sy = 0.f;
                #pragma unroll
                for (int mi = 0; mi < 2; mi++) {
                    sx += fmaxf(acc1[mi][ni][0] + acc2[mi][ni][0] * INV + bx, 0.f)
                        + fmaxf(acc1[mi][ni][2] + acc2[mi][ni][2] * INV + bx, 0.f);
                    sy += fmaxf(acc1[mi][ni][1] + acc2[mi][ni][1] * INV + by, 0.f)
                        + fmaxf(acc1[mi][ni][3] + acc2[mi][ni][3] * INV + by, 0.f);
                }
                sx += __shfl_xor_sync(0xFFFFFFFFu, sx, 16);
                sy += __shfl_xor_sync(0xFFFFFFFFu, sy, 16);
                sx += __shfl_xor_sync(0xFFFFFFFFu, sx, 8);
                sy += __shfl_xor_sync(0xFFFFFFFFu, sy, 8);
                sx += __shfl_xor_sync(0xFFFFFFFFu, sx, 4);
                sy += __shfl_xor_sync(0xFFFFFFFFu, sy, 4);
                if (g == 0) {
                    atomicAdd(&g_part[b * DIM + col], sx);
                    atomicAdd(&g_part[b * DIM + col + 1], sy);
                }
            }
        } else {
            const bool relu = (mode == 1);
            #pragma unroll
            for (int mi = 0; mi < 2; mi++) {
                const int r0 = token0 + wm * 32 + mi * 16 + g;
                #pragma unroll
                for (int ni = 0; ni < 4; ni++) {
                    const int col = wn * 32 + ni * 8 + 2 * t4;
                    const float bx = sm[col], by = sm[col + 1];
                    float c0 = acc1[mi][ni][0] + acc2[mi][ni][0] * INV + bx;
                    float c1 = acc1[mi][ni][1] + acc2[mi][ni][1] * INV + by;
                    float c2 = acc1[mi][ni][2] + acc2[mi][ni][2] * INV + bx;
                    float c3 = acc1[mi][ni][3] + acc2[mi][ni][3] * INV + by;
                    if (relu) {
                        c0 = fmaxf(c0, 0.f); c1 = fmaxf(c1, 0.f);
                        c2 = fmaxf(c2, 0.f); c3 = fmaxf(c3, 0.f);
                    }
                    *(__half2*)(out + (size_t)r0 * DIM + col) = __floats2half2_rn(c0, c1);
                    *(__half2*)(out + (size_t)(r0 + 8) * DIM + col) = __floats2half2_rn(c2, c3);
                }
            }
        }

        CP_WAIT0();         // next raw tile landed
        __syncthreads();    // all warps done with A before next build
    }
}

// ---------------------------------------------------------------------------
// Classifier: pooled mean -> relu(P@W1+b1) @ W2 + b2
// ---------------------------------------------------------------------------
__global__ __launch_bounds__(128) void cls_kernel(
    const float* __restrict__ w1, const float* __restrict__ b1,
    const float* __restrict__ w2, const float* __restrict__ b2,
    float* __restrict__ out)
{
    __shared__ float P[128];
    __shared__ float C1[64];
    const int b = blockIdx.x, tid = threadIdx.x;
    P[tid] = g_part[b * DIM + tid] * (1.0f / (float)SEQ);
    __syncthreads();
    if (tid < 64) {
        float a = b1[tid];
        #pragma unroll 8
        for (int k = 0; k < 128; k++) a += P[k] * w1[k * 64 + tid];
        C1[tid] = fmaxf(a, 0.f);
    }
    __syncthreads();
    if (tid < 3) {
        float a = b2[tid];
        #pragma unroll
        for (int k = 0; k < 64; k++) a += C1[k] * w2[k * 3 + tid];
        out[b * 3 + tid] = a;
    }
}

extern "C" void kernel_launch(void* const* d_in, const int* in_sizes, int n_in,
                              void* d_out, int out_size)
{
    const float* x      = (const float*)d_in[0];
    const float* enc_w1 = (const float*)d_in[1];
    const float* enc_b1 = (const float*)d_in[2];
    const float* enc_w2 = (const float*)d_in[3];
    const float* enc_b2 = (const float*)d_in[4];
    const float* gc1_w  = (const float*)d_in[5];
    const float* gc1_b  = (const float*)d_in[6];
    const float* gc2_w  = (const float*)d_in[7];
    const float* gc2_b  = (const float*)d_in[8];
    const float* gc3_w  = (const float*)d_in[9];
    const float* gc3_b  = (const float*)d_in[10];
    const float* cls_w1 = (const float*)d_in[11];
    const float* cls_b1 = (const float*)d_in[12];
    const float* cls_w2 = (const float*)d_in[13];
    const float* cls_b2 = (const float*)d_in[14];
    float* out = (float*)d_out;

    void *p0, *p1, *pwh, *pwl;
    cudaGetSymbolAddress(&p0, g_h0);
    cudaGetSymbolAddress(&p1, g_h1);
    cudaGetSymbolAddress(&pwh, g_Whi);
    cudaGetSymbolAddress(&pwl, g_Wlo);
    __half* h0 = (__half*)p0;
    __half* h1 = (__half*)p1;
    const __half* Whi = (const __half*)pwh;
    const __half* Wlo = (const __half*)pwl;

    const size_t stage_sm = 4096 + 16384 + 32768 + 32768 + 66 * 256;  // 102912 B
    cudaFuncSetAttribute(stage_kernel, cudaFuncAttributeMaxDynamicSharedMemorySize, (int)stage_sm);
    cudaFuncSetAttribute(stage_kernel, cudaFuncAttributePreferredSharedMemoryCarveout, 100);

    prep_w<<<4, 256>>>(enc_w2, gc1_w, gc2_w, gc3_w);
    zero_part<<<16, 256>>>();

    stage_kernel<<<GRID, 256, stage_sm>>>(x,  Whi + 0 * DIM * DIM, Wlo + 0 * DIM * DIM, enc_b2, enc_w1, enc_b1, h0, 0);
    stage_kernel<<<GRID, 256, stage_sm>>>(h0, Whi + 1 * DIM * DIM, Wlo + 1 * DIM * DIM, gc1_b,  enc_w1, enc_b1, h1, 1);
    stage_kernel<<<GRID, 256, stage_sm>>>(h1, Whi + 2 * DIM * DIM, Wlo + 2 * DIM * DIM, gc2_b,  enc_w1, enc_b1, h0, 1);
    stage_kernel<<<GRID, 256, stage_sm>>>(h0, Whi + 3 * DIM * DIM, Wlo + 3 * DIM * DIM, gc3_b,  enc_w1, enc_b1, h1, 2);
    cls_kernel<<<NB, 128>>>(cls_w1, cls_b1, cls_w2, cls_b2, out);
}

// round 8
// speedup vs baseline: 2.0093x; 1.0682x over previous
#include <cuda_runtime.h>
#include <cuda_fp16.h>
#include <cstdint>

#define SEQ 2048
#define NB  32
#define DIM 128
#define NTOK (NB*SEQ)
#define TOK 128
#define NTILES (NTOK/TOK)      // 512
#define GRID 128               // 4 tiles per CTA, exact balance

// ---------------- scratch (no allocations allowed) ----------------
__device__ __align__(16) __half g_h0[NTOK*DIM];
__device__ __align__(16) __half g_h1[NTOK*DIM];
__device__ float g_part[NB*DIM];
// prepared weight images: fp16 hi / scaled-lo, [n][k], 16B-chunk swizzle baked
__device__ __align__(16) __half g_Whi[4][DIM*DIM];
__device__ __align__(16) __half g_Wlo[4][DIM*DIM];

// ---------------- helpers ----------------
__device__ __forceinline__ uint32_t smem_u32(const void* p) {
    uint32_t a;
    asm("{ .reg .u64 t; cvta.to.shared.u64 t, %1; cvt.u32.u64 %0, t; }" : "=r"(a) : "l"(p));
    return a;
}
__device__ __forceinline__ void sts128(uint32_t addr, uint4 v) {
    asm volatile("st.shared.v4.b32 [%0], {%1,%2,%3,%4};" :: "r"(addr), "r"(v.x), "r"(v.y), "r"(v.z), "r"(v.w) : "memory");
}
__device__ __forceinline__ uint4 lds128(uint32_t addr) {
    uint4 v;
    asm volatile("ld.shared.v4.b32 {%0,%1,%2,%3}, [%4];"
        : "=r"(v.x), "=r"(v.y), "=r"(v.z), "=r"(v.w) : "r"(addr));
    return v;
}
__device__ __forceinline__ void cpasync16(uint32_t dst, const void* src) {
    asm volatile("cp.async.cg.shared.global [%0], [%1], 16;" :: "r"(dst), "l"(src) : "memory");
}
#define CP_COMMIT() asm volatile("cp.async.commit_group;" ::: "memory")
#define CP_WAIT0()  asm volatile("cp.async.wait_group 0;" ::: "memory")
#define LDMX4(r, addr) \
    asm volatile("ldmatrix.sync.aligned.m8n8.x4.shared.b16 {%0,%1,%2,%3}, [%4];" \
        : "=r"((r)[0]), "=r"((r)[1]), "=r"((r)[2]), "=r"((r)[3]) : "r"(addr))
__device__ __forceinline__ void mma16816(float* d, const uint32_t* a, const uint32_t* b) {
    asm volatile(
        "mma.sync.aligned.m16n8k16.row.col.f32.f16.f16.f32 "
        "{%0,%1,%2,%3}, {%4,%5,%6,%7}, {%8,%9}, {%0,%1,%2,%3};"
        : "+f"(d[0]), "+f"(d[1]), "+f"(d[2]), "+f"(d[3])
        : "r"(a[0]), "r"(a[1]), "r"(a[2]), "r"(a[3]), "r"(b[0]), "r"(b[1]));
}
// swizzled byte offset inside a [rows][128 fp16] tile: 256B rows, 16B chunks
__device__ __forceinline__ uint32_t tswz(int row, int kchunk) {
    return (uint32_t)(row * 256 + ((kchunk ^ (row & 7)) << 4));
}
__device__ __forceinline__ uint32_t packh(float a, float b) {
    __half2 t = __floats2half2_rn(a, b);
    return *reinterpret_cast<uint32_t*>(&t);
}

// ---------------------------------------------------------------------------
// Weight prep (+ zero pool partials): fp32 [k][n] -> fp16 hi + lo*2^10, [n][k]
// ---------------------------------------------------------------------------
__global__ void prep_w(const float* __restrict__ w0, const float* __restrict__ w1,
                       const float* __restrict__ w2, const float* __restrict__ w3)
{
    const float* ws[4] = {w0, w1, w2, w3};
    const float* w = ws[blockIdx.x];
    __half* bh = g_Whi[blockIdx.x];
    __half* bl = g_Wlo[blockIdx.x];
    if (blockIdx.x == 0) {
        for (int i = threadIdx.x; i < NB * DIM; i += blockDim.x) g_part[i] = 0.f;
    }
    for (int c = threadIdx.x; c < 2048; c += blockDim.x) {
        const int n = c >> 4, kc = c & 15, k0 = kc * 8;
        const int base = n * 128 + ((kc ^ (n & 7)) << 3);
        #pragma unroll
        for (int j = 0; j < 8; j++) {
            const float v = w[(k0 + j) * DIM + n];
            const __half hi = __float2half_rn(v);
            bh[base + j] = hi;
            bl[base + j] = __float2half_rn((v - __half2float(hi)) * 1024.0f);
        }
    }
}

// ---------------------------------------------------------------------------
// Persistent stage kernel: TOK=128 tile, 1 CTA/SM, warp grid 2(m)x4(n),
// warp tile 64x32. B images resident; next raw tile prefetched during MMA.
// mode 0 = encoder, mode 1 = gc (store), mode 2 = gc + fused mean-pool
// ---------------------------------------------------------------------------
__global__ __launch_bounds__(256, 1)
void stage_kernel(const void* __restrict__ in_v,
                  const __half* __restrict__ Whi_g,
                  const __half* __restrict__ Wlo_g,
                  const float* __restrict__ bias,
                  const float* __restrict__ w1, const float* __restrict__ b1,
                  __half* __restrict__ out, int mode)
{
    extern __shared__ float sm[];
    const int tid = threadIdx.x;
    const int wid = tid >> 5, lid = tid & 31;
    const uint32_t smb = smem_u32(sm);
    const uint32_t AS   = smb + 4096;        // 32KB  (128 x 256B)
    const uint32_t BhS  = AS + 32768;        // 32KB
    const uint32_t BlS  = BhS + 32768;       // 32KB
    const uint32_t rawS = BlS + 32768;       // 33.3KB (130 x 256B)

    // ---- prologue: B hi/lo images + first raw tile ----
    {
        const char* sh = (const char*)Whi_g;
        const char* sl = (const char*)Wlo_g;
        #pragma unroll
        for (int it = 0; it < 8; it++) {
            const int i = tid + it * 256;
            cpasync16(BhS + i * 16, sh + i * 16);
            cpasync16(BlS + i * 16, sl + i * 16);
        }
    }
    if (mode != 0) {
        const __half* hin = (const __half*)in_v;
        const int tok0 = blockIdx.x * TOK, s0 = tok0 & (SEQ - 1), bb = tok0 - s0;
        for (int i = tid; i < 130 * 16; i += 256) {
            const int row = i >> 4, c = i & 15;
            const int s = s0 - 1 + row;
            const uint32_t dst = rawS + tswz(row, c);
            if (s >= 0 && s < SEQ) cpasync16(dst, hin + (size_t)(bb + s) * DIM + c * 8);
            else                   sts128(dst, make_uint4(0, 0, 0, 0));
        }
    }
    CP_COMMIT();

    if (tid < 128) sm[tid] = bias[tid];
    if (mode == 0) {
        for (int i = tid; i < 768; i += 256) sm[128 + i] = w1[i];
        if (tid < 128) sm[896 + tid] = b1[tid];
    }
    CP_WAIT0();
    __syncthreads();

    const int r = tid >> 1, q = tid & 1;           // A-build: 2 threads/row
    const int wm = wid & 1, wn = wid >> 1;         // warp grid 2m x 4n
    const int g = lid >> 2, t4 = lid & 3;
    const int arowl = ((lid >> 3) & 1) * 8 + (lid & 7);
    const int akcl  = lid >> 4;
    const int browl = (lid >> 4) * 8 + (lid & 7);
    const int bkcl  = (lid >> 3) & 1;
    const float INV = 1.0f / 1024.0f;

    for (int tile = blockIdx.x; tile < NTILES; tile += GRID) {
        const int token0 = tile * TOK;
        const int s0 = token0 & (SEQ - 1);

        // ---- build A fp16 tile (128 x 128), swizzled ----
        if (mode != 0) {
            const int s_out = s0 + r;
            const float scale = (s_out == 0 || s_out == SEQ - 1) ? 0.5f : (1.0f / 3.0f);
            #pragma unroll
            for (int ch = 0; ch < 8; ch++) {
                const int c = q * 8 + ch;
                const uint4 u0 = lds128(rawS + tswz(r,     c));
                const uint4 u1 = lds128(rawS + tswz(r + 1, c));
                const uint4 u2 = lds128(rawS + tswz(r + 2, c));
                uint4 o;
                const uint32_t* p0 = &u0.x;
                const uint32_t* p1 = &u1.x;
                const uint32_t* p2 = &u2.x;
                uint32_t* po = &o.x;
                #pragma unroll
                for (int wd = 0; wd < 4; wd++) {
                    float2 f0 = __half22float2(*(const __half2*)&p0[wd]);
                    float2 f1 = __half22float2(*(const __half2*)&p1[wd]);
                    float2 f2 = __half22float2(*(const __half2*)&p2[wd]);
                    po[wd] = packh((f0.x + f1.x + f2.x) * scale,
                                   (f0.y + f1.y + f2.y) * scale);
                }
                sts128(AS + tswz(r, c), o);
            }
        } else {
            const float* x = (const float*)in_v;
            float xv[6];
            const float* xr = x + (size_t)(token0 + r) * 6;
            #pragma unroll
            for (int k = 0; k < 6; k++) xv[k] = xr[k];
            #pragma unroll
            for (int ch = 0; ch < 8; ch++) {
                const int c = q * 8 + ch;
                const int k0 = c * 8;
                uint4 o;
                uint32_t* po = &o.x;
                #pragma unroll
                for (int wd = 0; wd < 4; wd++) {
                    float v0, v1;
                    {
                        const int cc = k0 + wd * 2;
                        float a = sm[896 + cc];
                        #pragma unroll
                        for (int k = 0; k < 6; k++) a += xv[k] * sm[128 + k * 128 + cc];
                        v0 = fmaxf(a, 0.f);
                    }
                    {
                        const int cc = k0 + wd * 2 + 1;
                        float a = sm[896 + cc];
                        #pragma unroll
                        for (int k = 0; k < 6; k++) a += xv[k] * sm[128 + k * 128 + cc];
                        v1 = fmaxf(a, 0.f);
                    }
                    po[wd] = packh(v0, v1);
                }
                sts128(AS + tswz(r, c), o);
            }
        }
        __syncthreads();   // A built; raw buffer free

        // ---- prefetch next raw tile (overlaps MMA below) ----
        {
            const int tn = tile + GRID;
            if (mode != 0 && tn < NTILES) {
                const __half* hin = (const __half*)in_v;
                const int tok0n = tn * TOK, s0n = tok0n & (SEQ - 1), bbn = tok0n - s0n;
                for (int i = tid; i < 130 * 16; i += 256) {
                    const int row = i >> 4, c = i & 15;
                    const int s = s0n - 1 + row;
                    const uint32_t dst = rawS + tswz(row, c);
                    if (s >= 0 && s < SEQ) cpasync16(dst, hin + (size_t)(bbn + s) * DIM + c * 8);
                    else                   sts128(dst, make_uint4(0, 0, 0, 0));
                }
            }
            CP_COMMIT();
        }

        // ---- warp-level 2-product GEMM: warp tile 64 rows x 32 cols ----
        float acc1[4][4][4], acc2[4][4][4];
        #pragma unroll
        for (int mi = 0; mi < 4; mi++)
            #pragma unroll
            for (int ni = 0; ni < 4; ni++)
                #pragma unroll
                for (int j = 0; j < 4; j++) { acc1[mi][ni][j] = 0.f; acc2[mi][ni][j] = 0.f; }

        #pragma unroll
        for (int ks = 0; ks < 8; ks++) {
            uint32_t ah[4][4];
            #pragma unroll
            for (int mi = 0; mi < 4; mi++) {
                const int row = wm * 64 + mi * 16 + arowl;
                LDMX4(ah[mi], AS + tswz(row, ks * 2 + akcl));
            }
            #pragma unroll
            for (int p = 0; p < 2; p++) {
                const int nrow = wn * 32 + p * 16 + browl;
                const uint32_t boff = tswz(nrow, ks * 2 + bkcl);
                uint32_t bh[4], bl[4];
                LDMX4(bh, BhS + boff);
                LDMX4(bl, BlS + boff);
                #pragma unroll
                for (int hn = 0; hn < 2; hn++) {
                    const int ni = p * 2 + hn;
                    #pragma unroll
                    for (int mi = 0; mi < 4; mi++) {
                        mma16816(acc1[mi][ni], ah[mi], &bh[hn * 2]);
                        mma16816(acc2[mi][ni], ah[mi], &bl[hn * 2]);
                    }
                }
            }
        }

        // ---- epilogue ----
        if (mode == 2) {
            const int b = token0 >> 11;
            #pragma unroll
            for (int ni = 0; ni < 4; ni++) {
                const int col = wn * 32 + ni * 8 + 2 * t4;
                const float bx = sm[col], by = sm[col + 1];
                float sx = 0.f, sy = 0.f;
                #pragma unroll
                for (int mi = 0; mi < 4; mi++) {
                    sx += fmaxf(acc1[mi][ni][0] + acc2[mi][ni][0] * INV + bx, 0.f)
                        + fmaxf(acc1[mi][ni][2] + acc2[mi][ni][2] * INV + bx, 0.f);
                    sy += fmaxf(acc1[mi][ni][1] + acc2[mi][ni][1] * INV + by, 0.f)
                        + fmaxf(acc1[mi][ni][3] + acc2[mi][ni][3] * INV + by, 0.f);
                }
                sx += __shfl_xor_sync(0xFFFFFFFFu, sx, 16);
                sy += __shfl_xor_sync(0xFFFFFFFFu, sy, 16);
                sx += __shfl_xor_sync(0xFFFFFFFFu, sx, 8);
                sy += __shfl_xor_sync(0xFFFFFFFFu, sy, 8);
                sx += __shfl_xor_sync(0xFFFFFFFFu, sx, 4);
                sy += __shfl_xor_sync(0xFFFFFFFFu, sy, 4);
                if (g == 0) {
                    atomicAdd(&g_part[b * DIM + col], sx);
                    atomicAdd(&g_part[b * DIM + col + 1], sy);
                }
            }
        } else {
            const bool relu = (mode == 1);
            #pragma unroll
            for (int mi = 0; mi < 4; mi++) {
                const int r0 = token0 + wm * 64 + mi * 16 + g;
                #pragma unroll
                for (int ni = 0; ni < 4; ni++) {
                    const int col = wn * 32 + ni * 8 + 2 * t4;
                    const float bx = sm[col], by = sm[col + 1];
                    float c0 = acc1[mi][ni][0] + acc2[mi][ni][0] * INV + bx;
                    float c1 = acc1[mi][ni][1] + acc2[mi][ni][1] * INV + by;
                    float c2 = acc1[mi][ni][2] + acc2[mi][ni][2] * INV + bx;
                    float c3 = acc1[mi][ni][3] + acc2[mi][ni][3] * INV + by;
                    if (relu) {
                        c0 = fmaxf(c0, 0.f); c1 = fmaxf(c1, 0.f);
                        c2 = fmaxf(c2, 0.f); c3 = fmaxf(c3, 0.f);
                    }
                    *(__half2*)(out + (size_t)r0 * DIM + col) = __floats2half2_rn(c0, c1);
                    *(__half2*)(out + (size_t)(r0 + 8) * DIM + col) = __floats2half2_rn(c2, c3);
                }
            }
        }

        CP_WAIT0();         // next raw tile landed
        __syncthreads();    // all warps done with A before next build
    }
}

// ---------------------------------------------------------------------------
// Classifier: pooled mean -> relu(P@W1+b1) @ W2 + b2
// ---------------------------------------------------------------------------
__global__ __launch_bounds__(128) void cls_kernel(
    const float* __restrict__ w1, const float* __restrict__ b1,
    const float* __restrict__ w2, const float* __restrict__ b2,
    float* __restrict__ out)
{
    __shared__ float P[128];
    __shared__ float C1[64];
    const int b = blockIdx.x, tid = threadIdx.x;
    P[tid] = g_part[b * DIM + tid] * (1.0f / (float)SEQ);
    __syncthreads();
    if (tid < 64) {
        float a = b1[tid];
        #pragma unroll 8
        for (int k = 0; k < 128; k++) a += P[k] * w1[k * 64 + tid];
        C1[tid] = fmaxf(a, 0.f);
    }
    __syncthreads();
    if (tid < 3) {
        float a = b2[tid];
        #pragma unroll
        for (int k = 0; k < 64; k++) a += C1[k] * w2[k * 3 + tid];
        out[b * 3 + tid] = a;
    }
}

extern "C" void kernel_launch(void* const* d_in, const int* in_sizes, int n_in,
                              void* d_out, int out_size)
{
    const float* x      = (const float*)d_in[0];
    const float* enc_w1 = (const float*)d_in[1];
    const float* enc_b1 = (const float*)d_in[2];
    const float* enc_w2 = (const float*)d_in[3];
    const float* enc_b2 = (const float*)d_in[4];
    const float* gc1_w  = (const float*)d_in[5];
    const float* gc1_b  = (const float*)d_in[6];
    const float* gc2_w  = (const float*)d_in[7];
    const float* gc2_b  = (const float*)d_in[8];
    const float* gc3_w  = (const float*)d_in[9];
    const float* gc3_b  = (const float*)d_in[10];
    const float* cls_w1 = (const float*)d_in[11];
    const float* cls_b1 = (const float*)d_in[12];
    const float* cls_w2 = (const float*)d_in[13];
    const float* cls_b2 = (const float*)d_in[14];
    float* out = (float*)d_out;

    void *p0, *p1, *pwh, *pwl;
    cudaGetSymbolAddress(&p0, g_h0);
    cudaGetSymbolAddress(&p1, g_h1);
    cudaGetSymbolAddress(&pwh, g_Whi);
    cudaGetSymbolAddress(&pwl, g_Wlo);
    __half* h0 = (__half*)p0;
    __half* h1 = (__half*)p1;
    const __half* Whi = (const __half*)pwh;
    const __half* Wlo = (const __half*)pwl;

    const size_t stage_sm = 4096 + 32768 * 3 + 130 * 256;  // 135680 B
    cudaFuncSetAttribute(stage_kernel, cudaFuncAttributeMaxDynamicSharedMemorySize, (int)stage_sm);
    cudaFuncSetAttribute(stage_kernel, cudaFuncAttributePreferredSharedMemoryCarveout, 100);

    prep_w<<<4, 256>>>(enc_w2, gc1_w, gc2_w, gc3_w);

    stage_kernel<<<GRID, 256, stage_sm>>>(x,  Whi + 0 * DIM * DIM, Wlo + 0 * DIM * DIM, enc_b2, enc_w1, enc_b1, h0, 0);
    stage_kernel<<<GRID, 256, stage_sm>>>(h0, Whi + 1 * DIM * DIM, Wlo + 1 * DIM * DIM, gc1_b,  enc_w1, enc_b1, h1, 1);
    stage_kernel<<<GRID, 256, stage_sm>>>(h1, Whi + 2 * DIM * DIM, Wlo + 2 * DIM * DIM, gc2_b,  enc_w1, enc_b1, h0, 1);
    stage_kernel<<<GRID, 256, stage_sm>>>(h0, Whi + 3 * DIM * DIM, Wlo + 3 * DIM * DIM, gc3_b,  enc_w1, enc_b1, h1, 2);
    cls_kernel<<<NB, 128>>>(cls_w1, cls_b1, cls_w2, cls_b2, out);
}

// round 9
// speedup vs baseline: 2.0470x; 1.0187x over previous
#include <cuda_runtime.h>
#include <cuda_fp16.h>
#include <cstdint>

#define SEQ 2048
#define NB  32
#define DIM 128
#define NTOK (NB*SEQ)
#define TOK 128
#define NTILES (NTOK/TOK)      // 512
#define GRID 128               // 4 tiles per CTA, exact balance

// ---------------- scratch (no allocations allowed) ----------------
__device__ __align__(16) __half g_h0[NTOK*DIM];
__device__ __align__(16) __half g_h1[NTOK*DIM];
__device__ float g_part[NB*DIM];
// prepared weight images: fp16 hi / scaled-lo, [n][k], 16B-chunk swizzle baked
__device__ __align__(16) __half g_Whi[4][DIM*DIM];
__device__ __align__(16) __half g_Wlo[4][DIM*DIM];

// ---------------- helpers ----------------
__device__ __forceinline__ uint32_t smem_u32(const void* p) {
    uint32_t a;
    asm("{ .reg .u64 t; cvta.to.shared.u64 t, %1; cvt.u32.u64 %0, t; }" : "=r"(a) : "l"(p));
    return a;
}
__device__ __forceinline__ void sts128(uint32_t addr, uint4 v) {
    asm volatile("st.shared.v4.b32 [%0], {%1,%2,%3,%4};" :: "r"(addr), "r"(v.x), "r"(v.y), "r"(v.z), "r"(v.w) : "memory");
}
__device__ __forceinline__ uint4 lds128(uint32_t addr) {
    uint4 v;
    asm volatile("ld.shared.v4.b32 {%0,%1,%2,%3}, [%4];"
        : "=r"(v.x), "=r"(v.y), "=r"(v.z), "=r"(v.w) : "r"(addr));
    return v;
}
__device__ __forceinline__ void cpasync16(uint32_t dst, const void* src) {
    asm volatile("cp.async.cg.shared.global [%0], [%1], 16;" :: "r"(dst), "l"(src) : "memory");
}
#define CP_COMMIT() asm volatile("cp.async.commit_group;" ::: "memory")
#define CP_WAIT0()  asm volatile("cp.async.wait_group 0;" ::: "memory")
#define LDMX4(r, addr) \
    asm volatile("ldmatrix.sync.aligned.m8n8.x4.shared.b16 {%0,%1,%2,%3}, [%4];" \
        : "=r"((r)[0]), "=r"((r)[1]), "=r"((r)[2]), "=r"((r)[3]) : "r"(addr))
__device__ __forceinline__ void mma16816(float* d, const uint32_t* a, const uint32_t* b) {
    asm volatile(
        "mma.sync.aligned.m16n8k16.row.col.f32.f16.f16.f32 "
        "{%0,%1,%2,%3}, {%4,%5,%6,%7}, {%8,%9}, {%0,%1,%2,%3};"
        : "+f"(d[0]), "+f"(d[1]), "+f"(d[2]), "+f"(d[3])
        : "r"(a[0]), "r"(a[1]), "r"(a[2]), "r"(a[3]), "r"(b[0]), "r"(b[1]));
}
// swizzled byte offset inside a [rows][128 fp16] tile: 256B rows, 16B chunks
__device__ __forceinline__ uint32_t tswz(int row, int kchunk) {
    return (uint32_t)(row * 256 + ((kchunk ^ (row & 7)) << 4));
}
__device__ __forceinline__ uint32_t packh(float a, float b) {
    __half2 t = __floats2half2_rn(a, b);
    return *reinterpret_cast<uint32_t*>(&t);
}

// ---------------------------------------------------------------------------
// Weight prep (+ zero pool partials): fp32 [k][n] -> fp16 hi + lo*2^10, [n][k]
// ---------------------------------------------------------------------------
__global__ void prep_w(const float* __restrict__ w0, const float* __restrict__ w1,
                       const float* __restrict__ w2, const float* __restrict__ w3)
{
    const float* ws[4] = {w0, w1, w2, w3};
    const float* w = ws[blockIdx.x];
    __half* bh = g_Whi[blockIdx.x];
    __half* bl = g_Wlo[blockIdx.x];
    if (blockIdx.x == 0) {
        for (int i = threadIdx.x; i < NB * DIM; i += blockDim.x) g_part[i] = 0.f;
    }
    for (int c = threadIdx.x; c < 2048; c += blockDim.x) {
        const int n = c >> 4, kc = c & 15, k0 = kc * 8;
        const int base = n * 128 + ((kc ^ (n & 7)) << 3);
        #pragma unroll
        for (int j = 0; j < 8; j++) {
            const float v = w[(k0 + j) * DIM + n];
            const __half hi = __float2half_rn(v);
            bh[base + j] = hi;
            bl[base + j] = __float2half_rn((v - __half2float(hi)) * 1024.0f);
        }
    }
}

// ---------------------------------------------------------------------------
// Persistent stage kernel, software-pipelined: double-buffered A, ONE sync
// per tile; build of A(t+1) overlaps (via warp skew) MMA/epilogue of t.
// mode 0 = encoder, mode 1 = gc (store), mode 2 = gc + fused mean-pool
// ---------------------------------------------------------------------------
__global__ __launch_bounds__(256, 1)
void stage_kernel(const void* __restrict__ in_v,
                  const __half* __restrict__ Whi_g,
                  const __half* __restrict__ Wlo_g,
                  const float* __restrict__ bias,
                  const float* __restrict__ w1, const float* __restrict__ b1,
                  __half* __restrict__ out, int mode)
{
    extern __shared__ float sm[];
    const int tid = threadIdx.x;
    const int wid = tid >> 5, lid = tid & 31;
    const uint32_t smb = smem_u32(sm);
    const uint32_t A0S  = smb + 4096;        // 32KB (128 x 256B)
    const uint32_t A1S  = A0S + 32768;       // 32KB
    const uint32_t BhS  = A1S + 32768;       // 32KB
    const uint32_t BlS  = BhS + 32768;       // 32KB
    const uint32_t rawS = BlS + 32768;       // 33.3KB (130 x 256B)

    const int r = tid >> 1, q = tid & 1;           // A-build: 2 threads/row
    const int wm = wid & 1, wn = wid >> 1;         // warp grid 2m x 4n
    const int g = lid >> 2, t4 = lid & 3;
    const int arowl = ((lid >> 3) & 1) * 8 + (lid & 7);
    const int akcl  = lid >> 4;
    const int browl = (lid >> 4) * 8 + (lid & 7);
    const int bkcl  = (lid >> 3) & 1;
    const float INV = 1.0f / 1024.0f;

    // ---- A-build helpers (lambdas capture layout) ----
    auto issue_raw = [&](int tile) {
        const __half* hin = (const __half*)in_v;
        const int tok0 = tile * TOK, s0 = tok0 & (SEQ - 1), bb = tok0 - s0;
        for (int i = tid; i < 130 * 16; i += 256) {
            const int row = i >> 4, c = i & 15;
            const int s = s0 - 1 + row;
            const uint32_t dst = rawS + tswz(row, c);
            if (s >= 0 && s < SEQ) cpasync16(dst, hin + (size_t)(bb + s) * DIM + c * 8);
            else                   sts128(dst, make_uint4(0, 0, 0, 0));
        }
    };
    auto build_A = [&](int tile, uint32_t AS) {
        const int token0 = tile * TOK;
        if (mode != 0) {
            const int s0 = token0 & (SEQ - 1);
            const int s_out = s0 + r;
            const float scale = (s_out == 0 || s_out == SEQ - 1) ? 0.5f : (1.0f / 3.0f);
            #pragma unroll
            for (int ch = 0; ch < 8; ch++) {
                const int c = q * 8 + ch;
                const uint4 u0 = lds128(rawS + tswz(r,     c));
                const uint4 u1 = lds128(rawS + tswz(r + 1, c));
                const uint4 u2 = lds128(rawS + tswz(r + 2, c));
                uint4 o;
                const uint32_t* p0 = &u0.x;
                const uint32_t* p1 = &u1.x;
                const uint32_t* p2 = &u2.x;
                uint32_t* po = &o.x;
                #pragma unroll
                for (int wd = 0; wd < 4; wd++) {
                    float2 f0 = __half22float2(*(const __half2*)&p0[wd]);
                    float2 f1 = __half22float2(*(const __half2*)&p1[wd]);
                    float2 f2 = __half22float2(*(const __half2*)&p2[wd]);
                    po[wd] = packh((f0.x + f1.x + f2.x) * scale,
                                   (f0.y + f1.y + f2.y) * scale);
                }
                sts128(AS + tswz(r, c), o);
            }
        } else {
            const float* x = (const float*)in_v;
            float xv[6];
            const float* xr = x + (size_t)(token0 + r) * 6;
            #pragma unroll
            for (int k = 0; k < 6; k++) xv[k] = xr[k];
            #pragma unroll
            for (int ch = 0; ch < 8; ch++) {
                const int c = q * 8 + ch;
                const int k0 = c * 8;
                uint4 o;
                uint32_t* po = &o.x;
                #pragma unroll
                for (int wd = 0; wd < 4; wd++) {
                    float v0, v1;
                    {
                        const int cc = k0 + wd * 2;
                        float a = sm[896 + cc];
                        #pragma unroll
                        for (int k = 0; k < 6; k++) a += xv[k] * sm[128 + k * 128 + cc];
                        v0 = fmaxf(a, 0.f);
                    }
                    {
                        const int cc = k0 + wd * 2 + 1;
                        float a = sm[896 + cc];
                        #pragma unroll
                        for (int k = 0; k < 6; k++) a += xv[k] * sm[128 + k * 128 + cc];
                        v1 = fmaxf(a, 0.f);
                    }
                    po[wd] = packh(v0, v1);
                }
                sts128(AS + tswz(r, c), o);
            }
        }
    };

    // ---- prologue: B hi/lo images + raw(tile0), then build A(tile0) ----
    {
        const char* sh = (const char*)Whi_g;
        const char* sl = (const char*)Wlo_g;
        #pragma unroll
        for (int it = 0; it < 8; it++) {
            const int i = tid + it * 256;
            cpasync16(BhS + i * 16, sh + i * 16);
            cpasync16(BlS + i * 16, sl + i * 16);
        }
    }
    if (mode != 0) issue_raw(blockIdx.x);
    CP_COMMIT();
    if (tid < 128) sm[tid] = bias[tid];
    if (mode == 0) {
        for (int i = tid; i < 768; i += 256) sm[128 + i] = w1[i];
        if (tid < 128) sm[896 + tid] = b1[tid];
    }
    CP_WAIT0();
    __syncthreads();
    build_A(blockIdx.x, A0S);

    int ph = 0;
    for (int tile = blockIdx.x; tile < NTILES; tile += GRID, ph ^= 1) {
        const int token0 = tile * TOK;
        const int tnext = tile + GRID;

        __syncthreads();     // A(tile) visible; raw buffer free of readers

        // issue next raw tile (hidden under MMA)
        if (mode != 0 && tnext < NTILES) issue_raw(tnext);
        CP_COMMIT();

        const uint32_t AS = ph ? A1S : A0S;

        // ---- warp-level 2-product GEMM: warp tile 64 rows x 32 cols ----
        float acc1[4][4][4], acc2[4][4][4];
        #pragma unroll
        for (int mi = 0; mi < 4; mi++)
            #pragma unroll
            for (int ni = 0; ni < 4; ni++)
                #pragma unroll
                for (int j = 0; j < 4; j++) { acc1[mi][ni][j] = 0.f; acc2[mi][ni][j] = 0.f; }

        #pragma unroll
        for (int ks = 0; ks < 8; ks++) {
            uint32_t ah[4][4];
            #pragma unroll
            for (int mi = 0; mi < 4; mi++) {
                const int row = wm * 64 + mi * 16 + arowl;
                LDMX4(ah[mi], AS + tswz(row, ks * 2 + akcl));
            }
            #pragma unroll
            for (int p = 0; p < 2; p++) {
                const int nrow = wn * 32 + p * 16 + browl;
                const uint32_t boff = tswz(nrow, ks * 2 + bkcl);
                uint32_t bh[4], bl[4];
                LDMX4(bh, BhS + boff);
                LDMX4(bl, BlS + boff);
                #pragma unroll
                for (int hn = 0; hn < 2; hn++) {
                    const int ni = p * 2 + hn;
                    #pragma unroll
                    for (int mi = 0; mi < 4; mi++) {
                        mma16816(acc1[mi][ni], ah[mi], &bh[hn * 2]);
                        mma16816(acc2[mi][ni], ah[mi], &bl[hn * 2]);
                    }
                }
            }
        }

        // ---- epilogue ----
        if (mode == 2) {
            const int b = token0 >> 11;
            #pragma unroll
            for (int ni = 0; ni < 4; ni++) {
                const int col = wn * 32 + ni * 8 + 2 * t4;
                const float bx = sm[col], by = sm[col + 1];
                float sx = 0.f, sy = 0.f;
                #pragma unroll
                for (int mi = 0; mi < 4; mi++) {
                    sx += fmaxf(acc1[mi][ni][0] + acc2[mi][ni][0] * INV + bx, 0.f)
                        + fmaxf(acc1[mi][ni][2] + acc2[mi][ni][2] * INV + bx, 0.f);
                    sy += fmaxf(acc1[mi][ni][1] + acc2[mi][ni][1] * INV + by, 0.f)
                        + fmaxf(acc1[mi][ni][3] + acc2[mi][ni][3] * INV + by, 0.f);
                }
                sx += __shfl_xor_sync(0xFFFFFFFFu, sx, 16);
                sy += __shfl_xor_sync(0xFFFFFFFFu, sy, 16);
                sx += __shfl_xor_sync(0xFFFFFFFFu, sx, 8);
                sy += __shfl_xor_sync(0xFFFFFFFFu, sy, 8);
                sx += __shfl_xor_sync(0xFFFFFFFFu, sx, 4);
                sy += __shfl_xor_sync(0xFFFFFFFFu, sy, 4);
                if (g == 0) {
                    atomicAdd(&g_part[b * DIM + col], sx);
                    atomicAdd(&g_part[b * DIM + col + 1], sy);
                }
            }
        } else {
            const bool relu = (mode == 1);
            #pragma unroll
            for (int mi = 0; mi < 4; mi++) {
                const int r0 = token0 + wm * 64 + mi * 16 + g;
                #pragma unroll
                for (int ni = 0; ni < 4; ni++) {
                    const int col = wn * 32 + ni * 8 + 2 * t4;
                    const float bx = sm[col], by = sm[col + 1];
                    float c0 = acc1[mi][ni][0] + acc2[mi][ni][0] * INV + bx;
                    float c1 = acc1[mi][ni][1] + acc2[mi][ni][1] * INV + by;
                    float c2 = acc1[mi][ni][2] + acc2[mi][ni][2] * INV + bx;
                    float c3 = acc1[mi][ni][3] + acc2[mi][ni][3] * INV + by;
                    if (relu) {
                        c0 = fmaxf(c0, 0.f); c1 = fmaxf(c1, 0.f);
                        c2 = fmaxf(c2, 0.f); c3 = fmaxf(c3, 0.f);
                    }
                    *(__half2*)(out + (size_t)r0 * DIM + col) = __floats2half2_rn(c0, c1);
                    *(__half2*)(out + (size_t)(r0 + 8) * DIM + col) = __floats2half2_rn(c2, c3);
                }
            }
        }

        // ---- build A(t+1) into the other buffer (overlaps peers' MMA) ----
        if (tnext < NTILES) {
            CP_WAIT0();     // raw(t+1) landed
            build_A(tnext, ph ? A0S : A1S);
        }
    }
}

// ---------------------------------------------------------------------------
// Classifier: pooled mean -> relu(P@W1+b1) @ W2 + b2
// ---------------------------------------------------------------------------
__global__ __launch_bounds__(128) void cls_kernel(
    const float* __restrict__ w1, const float* __restrict__ b1,
    const float* __restrict__ w2, const float* __restrict__ b2,
    float* __restrict__ out)
{
    __shared__ float P[128];
    __shared__ float C1[64];
    const int b = blockIdx.x, tid = threadIdx.x;
    P[tid] = g_part[b * DIM + tid] * (1.0f / (float)SEQ);
    __syncthreads();
    if (tid < 64) {
        float a = b1[tid];
        #pragma unroll 8
        for (int k = 0; k < 128; k++) a += P[k] * w1[k * 64 + tid];
        C1[tid] = fmaxf(a, 0.f);
    }
    __syncthreads();
    if (tid < 3) {
        float a = b2[tid];
        #pragma unroll
        for (int k = 0; k < 64; k++) a += C1[k] * w2[k * 3 + tid];
        out[b * 3 + tid] = a;
    }
}

extern "C" void kernel_launch(void* const* d_in, const int* in_sizes, int n_in,
                              void* d_out, int out_size)
{
    const float* x      = (const float*)d_in[0];
    const float* enc_w1 = (const float*)d_in[1];
    const float* enc_b1 = (const float*)d_in[2];
    const float* enc_w2 = (const float*)d_in[3];
    const float* enc_b2 = (const float*)d_in[4];
    const float* gc1_w  = (const float*)d_in[5];
    const float* gc1_b  = (const float*)d_in[6];
    const float* gc2_w  = (const float*)d_in[7];
    const float* gc2_b  = (const float*)d_in[8];
    const float* gc3_w  = (const float*)d_in[9];
    const float* gc3_b  = (const float*)d_in[10];
    const float* cls_w1 = (const float*)d_in[11];
    const float* cls_b1 = (const float*)d_in[12];
    const float* cls_w2 = (const float*)d_in[13];
    const float* cls_b2 = (const float*)d_in[14];
    float* out = (float*)d_out;

    void *p0, *p1, *pwh, *pwl;
    cudaGetSymbolAddress(&p0, g_h0);
    cudaGetSymbolAddress(&p1, g_h1);
    cudaGetSymbolAddress(&pwh, g_Whi);
    cudaGetSymbolAddress(&pwl, g_Wlo);
    __half* h0 = (__half*)p0;
    __half* h1 = (__half*)p1;
    const __half* Whi = (const __half*)pwh;
    const __half* Wlo = (const __half*)pwl;

    const size_t stage_sm = 4096 + 32768 * 4 + 130 * 256;  // 168448 B
    cudaFuncSetAttribute(stage_kernel, cudaFuncAttributeMaxDynamicSharedMemorySize, (int)stage_sm);
    cudaFuncSetAttribute(stage_kernel, cudaFuncAttributePreferredSharedMemoryCarveout, 100);

    prep_w<<<4, 256>>>(enc_w2, gc1_w, gc2_w, gc3_w);

    stage_kernel<<<GRID, 256, stage_sm>>>(x,  Whi + 0 * DIM * DIM, Wlo + 0 * DIM * DIM, enc_b2, enc_w1, enc_b1, h0, 0);
    stage_kernel<<<GRID, 256, stage_sm>>>(h0, Whi + 1 * DIM * DIM, Wlo + 1 * DIM * DIM, gc1_b,  enc_w1, enc_b1, h1, 1);
    stage_kernel<<<GRID, 256, stage_sm>>>(h1, Whi + 2 * DIM * DIM, Wlo + 2 * DIM * DIM, gc2_b,  enc_w1, enc_b1, h0, 1);
    stage_kernel<<<GRID, 256, stage_sm>>>(h0, Whi + 3 * DIM * DIM, Wlo + 3 * DIM * DIM, gc3_b,  enc_w1, enc_b1, h1, 2);
    cls_kernel<<<NB, 128>>>(cls_w1, cls_b1, cls_w2, cls_b2, out);
}